// round 12
// baseline (speedup 1.0000x reference)
#include <cuda_runtime.h>
#include <cstddef>

#define N_NODES   50000
#define N_EDGES   800000
#define IN_CH     64
#define HIDDEN    128
#define NUM_GRAPHS 256

typedef unsigned long long u64;

// ---------------- scratch (static device globals; no allocation) ----------------
__device__ float g_agg1[(size_t)N_NODES * IN_CH];
__device__ float g_agg2[(size_t)N_NODES * HIDDEN];
__device__ float g_agg3[(size_t)N_NODES * HIDDEN];
__device__ float g_h1 [(size_t)N_NODES * HIDDEN];
__device__ float g_h2 [(size_t)N_NODES * HIDDEN];
__device__ float g_sums[(size_t)NUM_GRAPHS * HIDDEN];
// CSR-by-dst sort scratch
__device__ int   g_hist[N_NODES];
__device__ int   g_off [N_NODES + 1];
__device__ int   g_cursor[N_NODES];
__device__ int   g_src_sorted[N_EDGES];
__device__ float g_ea_sorted[(size_t)N_EDGES * 8];

// ---------------- packed f32x2 helpers (sm_103a FFMA2) ----------------
__device__ __forceinline__ u64 pack2(float lo, float hi) {
    u64 r;
    asm("mov.b64 %0, {%1, %2};" : "=l"(r) : "r"(__float_as_uint(lo)), "r"(__float_as_uint(hi)));
    return r;
}
__device__ __forceinline__ u64 fma2(u64 a, u64 b, u64 c) {
    u64 d;
    asm("fma.rn.f32x2 %0, %1, %2, %3;" : "=l"(d) : "l"(a), "l"(b), "l"(c));
    return d;
}
__device__ __forceinline__ float2 unpack2(u64 v) {
    unsigned lo, hi;
    asm("mov.b64 {%0, %1}, %2;" : "=r"(lo), "=r"(hi) : "l"(v));
    return make_float2(__uint_as_float(lo), __uint_as_float(hi));
}

// ---------------- vector reductions (sm_90+) ----------------
__device__ __forceinline__ void red_add_v4(float* addr, float4 v) {
    asm volatile("red.global.add.v4.f32 [%0], {%1,%2,%3,%4};"
                 :: "l"(addr), "f"(v.x), "f"(v.y), "f"(v.z), "f"(v.w) : "memory");
}

// ---------------- sort phase: CSR by dst ----------------
__global__ void zero_hist_kernel() {
    for (int i = blockIdx.x * blockDim.x + threadIdx.x; i < N_NODES; i += gridDim.x * blockDim.x)
        g_hist[i] = 0;
}
__global__ void hist_kernel(const int* __restrict__ ei) {
    const int* dstp = ei + N_EDGES;
    for (int e = blockIdx.x * blockDim.x + threadIdx.x; e < N_EDGES; e += gridDim.x * blockDim.x)
        atomicAdd(&g_hist[dstp[e]], 1);
}
__global__ void scan_kernel() {   // single block, 1024 threads
    __shared__ int part[1024];
    const int tid = threadIdx.x;
    const int CH = (N_NODES + 1023) / 1024;
    const int base = tid * CH;
    int s = 0;
    for (int i = 0; i < CH; i++) {
        int idx = base + i;
        if (idx < N_NODES) s += g_hist[idx];
    }
    part[tid] = s;
    __syncthreads();
    for (int d = 1; d < 1024; d <<= 1) {
        int v = (tid >= d) ? part[tid - d] : 0;
        __syncthreads();
        part[tid] += v;
        __syncthreads();
    }
    int run = (tid > 0) ? part[tid - 1] : 0;
    for (int i = 0; i < CH; i++) {
        int idx = base + i;
        if (idx < N_NODES) {
            int c = g_hist[idx];
            g_off[idx] = run;
            g_cursor[idx] = run;
            run += c;
        }
    }
    if (tid == 1023) g_off[N_NODES] = N_EDGES;
}
__global__ void scatter_kernel(const int* __restrict__ ei, const float* __restrict__ ea) {
    const int* srcp = ei;
    const int* dstp = ei + N_EDGES;
    const float4* ea4 = reinterpret_cast<const float4*>(ea);
    float4* eas4 = reinterpret_cast<float4*>(g_ea_sorted);
    for (int e = blockIdx.x * blockDim.x + threadIdx.x; e < N_EDGES; e += gridDim.x * blockDim.x) {
        const int d = dstp[e];
        const int pos = atomicAdd(&g_cursor[d], 1);
        g_src_sorted[pos] = srcp[e];
        eas4[(size_t)pos * 2]     = ea4[(size_t)e * 2];
        eas4[(size_t)pos * 2 + 1] = ea4[(size_t)e * 2 + 1];
    }
}

// ---------------- streaming CSR aggregation D=128: linear edge walk, depth-2 pipeline ----------------
// agg[n] = h[n] + sum_{e in CSR[n]} relu(h[src[e]] + ea[e]@We + be).  No atomics.
__global__ __launch_bounds__(256, 3)
void agg_kernel128(const float* __restrict__ h,
                   const float* __restrict__ We,
                   const float* __restrict__ be,
                   float* __restrict__ agg) {
    __shared__ __align__(16) float4 Wes4[8 * 32];
    __shared__ __align__(16) float4 bes4[32];
    for (int i = threadIdx.x; i < 8 * 32; i += blockDim.x)
        Wes4[i] = reinterpret_cast<const float4*>(We)[i];
    if (threadIdx.x < 32) bes4[threadIdx.x] = reinterpret_cast<const float4*>(be)[threadIdx.x];
    __syncthreads();

    const int lane = threadIdx.x & 31;
    float4 w[8];
#pragma unroll
    for (int k = 0; k < 8; k++) w[k] = Wes4[k * 32 + lane];
    const float4 bj = bes4[lane];

    const int wid = (blockIdx.x * blockDim.x + threadIdx.x) >> 5;
    const int nw  = (gridDim.x * blockDim.x) >> 5;
    const int per = (N_NODES + nw - 1) / nw;
    const int n0  = wid * per;
    const int n1  = (n0 + per < N_NODES) ? (n0 + per) : N_NODES;
    if (n0 >= n1) return;

    const float4* __restrict__ h4 = reinterpret_cast<const float4*>(h);
    const float4* __restrict__ eas4 = reinterpret_cast<const float4*>(g_ea_sorted);
    const int* __restrict__ srcs = g_src_sorted;

    const int estart = g_off[n0], eend = g_off[n1];
    int n = n0;
    int bnd = g_off[n0 + 1];
    float4 acc = make_float4(0.f, 0.f, 0.f, 0.f);

    if (estart < eend) {
        const int last = eend - 1;
        float4 xv0 = h4[(size_t)srcs[estart] * 32 + lane];
        int s1 = srcs[(estart + 1 <= last) ? estart + 1 : last];

        for (int e = estart; e < eend; ++e) {
            // depth-2 gather pipeline
            float4 xv1 = h4[(size_t)s1 * 32 + lane];
            const int i2 = (e + 2 <= last) ? e + 2 : last;
            const int s2 = srcs[i2];

            // flush completed nodes (warp-uniform; ~once per 16 edges)
            while (e >= bnd) {
                const float4 hv = h4[(size_t)n * 32 + lane];
                reinterpret_cast<float4*>(agg)[(size_t)n * 32 + lane] =
                    make_float4(hv.x + acc.x, hv.y + acc.y, hv.z + acc.z, hv.w + acc.w);
                acc = make_float4(0.f, 0.f, 0.f, 0.f);
                ++n;
                bnd = g_off[n + 1];
            }

            const float4 a0 = eas4[(size_t)e * 2];
            const float4 a1 = eas4[(size_t)e * 2 + 1];
            float ak[8] = {a0.x, a0.y, a0.z, a0.w, a1.x, a1.y, a1.z, a1.w};
            float4 t = bj;
#pragma unroll
            for (int k = 0; k < 8; k++) {
                t.x = fmaf(ak[k], w[k].x, t.x);
                t.y = fmaf(ak[k], w[k].y, t.y);
                t.z = fmaf(ak[k], w[k].z, t.z);
                t.w = fmaf(ak[k], w[k].w, t.w);
            }
            acc.x += fmaxf(xv0.x + t.x, 0.f);
            acc.y += fmaxf(xv0.y + t.y, 0.f);
            acc.z += fmaxf(xv0.z + t.z, 0.f);
            acc.w += fmaxf(xv0.w + t.w, 0.f);

            xv0 = xv1; s1 = s2;
        }
    }
    // final flush: current node gets acc, remaining nodes get h only
    for (; n < n1; ++n) {
        const float4 hv = h4[(size_t)n * 32 + lane];
        reinterpret_cast<float4*>(agg)[(size_t)n * 32 + lane] =
            make_float4(hv.x + acc.x, hv.y + acc.y, hv.z + acc.z, hv.w + acc.w);
        acc = make_float4(0.f, 0.f, 0.f, 0.f);
    }
}

// ---------------- streaming CSR aggregation D=64: float2 per lane ----------------
__global__ __launch_bounds__(256, 3)
void agg_kernel64(const float* __restrict__ h,
                  const float* __restrict__ We,
                  const float* __restrict__ be,
                  float* __restrict__ agg) {
    __shared__ __align__(16) float2 Wes2[8 * 32];
    __shared__ __align__(16) float2 bes2[32];
    for (int i = threadIdx.x; i < 8 * 32; i += blockDim.x)
        Wes2[i] = reinterpret_cast<const float2*>(We)[i];
    if (threadIdx.x < 32) bes2[threadIdx.x] = reinterpret_cast<const float2*>(be)[threadIdx.x];
    __syncthreads();

    const int lane = threadIdx.x & 31;
    float2 w[8];
#pragma unroll
    for (int k = 0; k < 8; k++) w[k] = Wes2[k * 32 + lane];
    const float2 bj = bes2[lane];

    const int wid = (blockIdx.x * blockDim.x + threadIdx.x) >> 5;
    const int nw  = (gridDim.x * blockDim.x) >> 5;
    const int per = (N_NODES + nw - 1) / nw;
    const int n0  = wid * per;
    const int n1  = (n0 + per < N_NODES) ? (n0 + per) : N_NODES;
    if (n0 >= n1) return;

    const float2* __restrict__ h2v = reinterpret_cast<const float2*>(h);
    const float4* __restrict__ eas4 = reinterpret_cast<const float4*>(g_ea_sorted);
    const int* __restrict__ srcs = g_src_sorted;

    const int estart = g_off[n0], eend = g_off[n1];
    int n = n0;
    int bnd = g_off[n0 + 1];
    float2 acc = make_float2(0.f, 0.f);

    if (estart < eend) {
        const int last = eend - 1;
        float2 xv0 = h2v[(size_t)srcs[estart] * 32 + lane];
        int s1 = srcs[(estart + 1 <= last) ? estart + 1 : last];

        for (int e = estart; e < eend; ++e) {
            float2 xv1 = h2v[(size_t)s1 * 32 + lane];
            const int i2 = (e + 2 <= last) ? e + 2 : last;
            const int s2 = srcs[i2];

            while (e >= bnd) {
                const float2 hv = h2v[(size_t)n * 32 + lane];
                reinterpret_cast<float2*>(agg)[(size_t)n * 32 + lane] =
                    make_float2(hv.x + acc.x, hv.y + acc.y);
                acc = make_float2(0.f, 0.f);
                ++n;
                bnd = g_off[n + 1];
            }

            const float4 a0 = eas4[(size_t)e * 2];
            const float4 a1 = eas4[(size_t)e * 2 + 1];
            float ak[8] = {a0.x, a0.y, a0.z, a0.w, a1.x, a1.y, a1.z, a1.w};
            float2 t = bj;
#pragma unroll
            for (int k = 0; k < 8; k++) {
                t.x = fmaf(ak[k], w[k].x, t.x);
                t.y = fmaf(ak[k], w[k].y, t.y);
            }
            acc.x += fmaxf(xv0.x + t.x, 0.f);
            acc.y += fmaxf(xv0.y + t.y, 0.f);

            xv0 = xv1; s1 = s2;
        }
    }
    for (; n < n1; ++n) {
        const float2 hv = h2v[(size_t)n * 32 + lane];
        reinterpret_cast<float2*>(agg)[(size_t)n * 32 + lane] =
            make_float2(hv.x + acc.x, hv.y + acc.y);
        acc = make_float2(0.f, 0.f);
    }
}

// ---------------- persistent node kernel: y = relu(agg @ W + b) ----------------
template <int K, bool POOL>
__global__ void node_kernel(const float* __restrict__ agg,
                            const float* __restrict__ W,
                            const float* __restrict__ b,
                            const int* __restrict__ batch,
                            float* __restrict__ out,
                            int ntiles) {
    extern __shared__ __align__(16) float sm[];
    float* Ws  = sm;               // K * 128
    float* ins = sm + K * 128;     // 64 * K
    const int tid = threadIdx.x;
    constexpr int K4 = K / 4;

    const float4* W4 = reinterpret_cast<const float4*>(W);
    float4* Ws4 = reinterpret_cast<float4*>(Ws);
    for (int i = tid; i < K * 32; i += 256) Ws4[i] = W4[i];

    const int w = tid >> 5, lane = tid & 31;
    const float4 bj = reinterpret_cast<const float4*>(b)[lane];
    const u64 bp0 = pack2(bj.x, bj.y), bp1 = pack2(bj.z, bj.w);
    const float4* a4 = reinterpret_cast<const float4*>(agg);
    float4* in4 = reinterpret_cast<float4*>(ins);

    for (int tile = blockIdx.x; tile < ntiles; tile += gridDim.x) {
        const int base = tile * 64;
        __syncthreads();
        for (int i = tid; i < 64 * K4; i += 256) {
            const int r = i / K4, c = i % K4;
            const int n = base + r;
            in4[i] = (n < N_NODES) ? a4[(size_t)n * K4 + c] : make_float4(0.f, 0.f, 0.f, 0.f);
        }
        __syncthreads();

        u64 acc0[8], acc1[8];
#pragma unroll
        for (int m = 0; m < 8; m++) { acc0[m] = bp0; acc1[m] = bp1; }

        const float* inrow = ins + (w * 8) * K;
#pragma unroll 1
        for (int k = 0; k < K; k += 4) {
            const float4 wv0 = Ws4[(k + 0) * 32 + lane];
            const float4 wv1 = Ws4[(k + 1) * 32 + lane];
            const float4 wv2 = Ws4[(k + 2) * 32 + lane];
            const float4 wv3 = Ws4[(k + 3) * 32 + lane];
            const u64 w00 = pack2(wv0.x, wv0.y), w01 = pack2(wv0.z, wv0.w);
            const u64 w10 = pack2(wv1.x, wv1.y), w11 = pack2(wv1.z, wv1.w);
            const u64 w20 = pack2(wv2.x, wv2.y), w21 = pack2(wv2.z, wv2.w);
            const u64 w30 = pack2(wv3.x, wv3.y), w31 = pack2(wv3.z, wv3.w);
#pragma unroll
            for (int m = 0; m < 8; m++) {
                const float4 iv = *reinterpret_cast<const float4*>(inrow + m * K + k);
                u64 t;
                t = pack2(iv.x, iv.x);
                acc0[m] = fma2(t, w00, acc0[m]);
                acc1[m] = fma2(t, w01, acc1[m]);
                t = pack2(iv.y, iv.y);
                acc0[m] = fma2(t, w10, acc0[m]);
                acc1[m] = fma2(t, w11, acc1[m]);
                t = pack2(iv.z, iv.z);
                acc0[m] = fma2(t, w20, acc0[m]);
                acc1[m] = fma2(t, w21, acc1[m]);
                t = pack2(iv.w, iv.w);
                acc0[m] = fma2(t, w30, acc0[m]);
                acc1[m] = fma2(t, w31, acc1[m]);
            }
        }

#pragma unroll
        for (int m = 0; m < 8; m++) {
            const int n = base + w * 8 + m;
            if (n < N_NODES) {
                const float2 lo = unpack2(acc0[m]);
                const float2 hi = unpack2(acc1[m]);
                float4 r;
                r.x = fmaxf(lo.x, 0.f);
                r.y = fmaxf(lo.y, 0.f);
                r.z = fmaxf(hi.x, 0.f);
                r.w = fmaxf(hi.y, 0.f);
                if (POOL) {
                    const int g = batch[n];
                    red_add_v4(&g_sums[(size_t)g * HIDDEN + lane * 4], r);
                } else {
                    reinterpret_cast<float4*>(out)[(size_t)n * 32 + lane] = r;
                }
            }
        }
    }
}

// ---------------- pool zero + final divide ----------------
__global__ void zero_pool_kernel() {
    int i = blockIdx.x * blockDim.x + threadIdx.x;
    if (i < NUM_GRAPHS * HIDDEN / 4)
        reinterpret_cast<float4*>(g_sums)[i] = make_float4(0.f, 0.f, 0.f, 0.f);
}
__global__ void div_kernel(const int* __restrict__ batch, float* __restrict__ out) {
    const int g = blockIdx.x;
    const int j = threadIdx.x;
    int lo = 0, hi = N_NODES;
    while (lo < hi) { int mid = (lo + hi) >> 1; if (batch[mid] < g) lo = mid + 1; else hi = mid; }
    const int first = lo;
    lo = first; hi = N_NODES;
    while (lo < hi) { int mid = (lo + hi) >> 1; if (batch[mid] < g + 1) lo = mid + 1; else hi = mid; }
    const float c = fmaxf((float)(lo - first), 1.0f);
    out[g * HIDDEN + j] = g_sums[g * HIDDEN + j] / c;
}

// ---------------- launch ----------------
extern "C" void kernel_launch(void* const* d_in, const int* in_sizes, int n_in,
                              void* d_out, int out_size) {
    const float* x     = (const float*)d_in[0];
    const int*   ei    = (const int*)d_in[1];
    const float* ea    = (const float*)d_in[2];
    const int*   batch = (const int*)d_in[3];
    const float *W1 = (const float*)d_in[4],  *b1 = (const float*)d_in[5];
    const float *We1= (const float*)d_in[6],  *be1= (const float*)d_in[7];
    const float *W2 = (const float*)d_in[8],  *b2 = (const float*)d_in[9];
    const float *We2= (const float*)d_in[10], *be2= (const float*)d_in[11];
    const float *W3 = (const float*)d_in[12], *b3 = (const float*)d_in[13];
    const float *We3= (const float*)d_in[14], *be3= (const float*)d_in[15];
    float* out = (float*)d_out;

    void* p;
    cudaGetSymbolAddress(&p, g_agg1); float* agg1 = (float*)p;
    cudaGetSymbolAddress(&p, g_agg2); float* agg2 = (float*)p;
    cudaGetSymbolAddress(&p, g_agg3); float* agg3 = (float*)p;
    cudaGetSymbolAddress(&p, g_h1);   float* h1   = (float*)p;
    cudaGetSymbolAddress(&p, g_h2);   float* h2   = (float*)p;

    const int smem64  = (64  * 128 + 64 * 64)  * 4;  // 48 KB
    const int smem128 = (128 * 128 + 64 * 128) * 4;  // 96 KB
    cudaFuncSetAttribute(node_kernel<64,  false>, cudaFuncAttributeMaxDynamicSharedMemorySize, smem64);
    cudaFuncSetAttribute(node_kernel<128, false>, cudaFuncAttributeMaxDynamicSharedMemorySize, smem128);
    cudaFuncSetAttribute(node_kernel<128, true >, cudaFuncAttributeMaxDynamicSharedMemorySize, smem128);

    const int AGG_GRID = 152 * 8;
    const int NTILES   = (N_NODES + 63) / 64;
    const int NGRID64  = 148 * 4;
    const int NGRID128 = 148 * 2;

    // ---- one-time sort (per launch): CSR by dst ----
    zero_hist_kernel<<<128, 256>>>();                                                   // 1
    hist_kernel<<<512, 256>>>(ei);                                                      // 2
    scan_kernel<<<1, 1024>>>();                                                         // 3
    scatter_kernel<<<512, 256>>>(ei, ea);                                               // 4

    // ---- layer 1 (64ch) ----
    agg_kernel64<<<AGG_GRID, 256>>>(x, We1, be1, agg1);                                 // 5
    node_kernel<64, false><<<NGRID64, 256, smem64>>>(agg1, W1, b1, nullptr, h1, NTILES);// 6
    // ---- layer 2 ----
    agg_kernel128<<<AGG_GRID, 256>>>(h1, We2, be2, agg2);                               // 7
    node_kernel<128, false><<<NGRID128, 256, smem128>>>(agg2, W2, b2, nullptr, h2, NTILES); // 8
    // ---- layer 3 + pool ----
    agg_kernel128<<<AGG_GRID, 256>>>(h2, We3, be3, agg3);                               // 9
    zero_pool_kernel<<<32, 256>>>();                                                    // 10
    node_kernel<128, true><<<NGRID128, 256, smem128>>>(agg3, W3, b3, batch, nullptr, NTILES); // 11
    div_kernel<<<NUM_GRAPHS, HIDDEN>>>(batch, out);                                     // 12
}

// round 13
// speedup vs baseline: 1.5247x; 1.5247x over previous
#include <cuda_runtime.h>
#include <cstddef>

#define N_NODES   50000
#define N_EDGES   800000
#define IN_CH     64
#define HIDDEN    128
#define NUM_GRAPHS 256

typedef unsigned long long u64;

// ---------------- scratch (static device globals; no allocation) ----------------
__device__ float g_agg1[(size_t)N_NODES * IN_CH];    // init = x,  += edge msgs
__device__ float g_agg2[(size_t)N_NODES * HIDDEN];   // init = h1, += edge msgs
__device__ float g_agg3[(size_t)N_NODES * HIDDEN];   // init = h2, += edge msgs
__device__ float g_h1 [(size_t)N_NODES * HIDDEN];
__device__ float g_h2 [(size_t)N_NODES * HIDDEN];
__device__ float g_sums[(size_t)NUM_GRAPHS * HIDDEN];

// ---------------- packed f32x2 helpers (sm_103a FFMA2) ----------------
__device__ __forceinline__ u64 pack2(float lo, float hi) {
    u64 r;
    asm("mov.b64 %0, {%1, %2};" : "=l"(r) : "r"(__float_as_uint(lo)), "r"(__float_as_uint(hi)));
    return r;
}
__device__ __forceinline__ u64 fma2(u64 a, u64 b, u64 c) {
    u64 d;
    asm("fma.rn.f32x2 %0, %1, %2, %3;" : "=l"(d) : "l"(a), "l"(b), "l"(c));
    return d;
}
__device__ __forceinline__ float2 unpack2(u64 v) {
    unsigned lo, hi;
    asm("mov.b64 {%0, %1}, %2;" : "=r"(lo), "=r"(hi) : "l"(v));
    return make_float2(__uint_as_float(lo), __uint_as_float(hi));
}

// ---------------- vector reductions (sm_90+) ----------------
__device__ __forceinline__ void red_add_v4(float* addr, float4 v) {
    asm volatile("red.global.add.v4.f32 [%0], {%1,%2,%3,%4};"
                 :: "l"(addr), "f"(v.x), "f"(v.y), "f"(v.z), "f"(v.w) : "memory");
}
__device__ __forceinline__ void red_add_v2(float* addr, float2 v) {
    asm volatile("red.global.add.v2.f32 [%0], {%1,%2};"
                 :: "l"(addr), "f"(v.x), "f"(v.y) : "memory");
}

// ---------------- init kernels ----------------
__global__ void init_agg1_kernel(const float* __restrict__ x) {   // agg1 = x
    const int n4 = N_NODES * IN_CH / 4;
    const float4* x4 = reinterpret_cast<const float4*>(x);
    for (int i = blockIdx.x * blockDim.x + threadIdx.x; i < n4; i += gridDim.x * blockDim.x)
        reinterpret_cast<float4*>(g_agg1)[i] = x4[i];
}
__global__ void zero_pool_kernel() {
    int i = blockIdx.x * blockDim.x + threadIdx.x;
    if (i < NUM_GRAPHS * HIDDEN / 4)
        reinterpret_cast<float4*>(g_sums)[i] = make_float4(0.f, 0.f, 0.f, 0.f);
}

// ---------------- edge kernel D=64: two edges per warp, depth-2 gather pipeline ----------------
__global__ __launch_bounds__(256, 4)
void edge_kernel64(const float* __restrict__ x,
                   const int* __restrict__ ei,
                   const float* __restrict__ ea,
                   const float* __restrict__ We,
                   const float* __restrict__ be,
                   float* __restrict__ agg) {
    __shared__ __align__(16) float4 Wes4[8 * 16];
    __shared__ __align__(16) float4 bes4[16];
    for (int i = threadIdx.x; i < 8 * 16; i += blockDim.x)
        Wes4[i] = reinterpret_cast<const float4*>(We)[i];
    if (threadIdx.x < 16) bes4[threadIdx.x] = reinterpret_cast<const float4*>(be)[threadIdx.x];
    __syncthreads();

    const int lane = threadIdx.x & 31;
    const int half = lane >> 4;
    const int sub  = lane & 15;
    float4 w[8];
#pragma unroll
    for (int k = 0; k < 8; k++) w[k] = Wes4[k * 16 + sub];
    const float4 bj = bes4[sub];

    const int wid = (blockIdx.x * blockDim.x + threadIdx.x) >> 5;
    const int nw  = (gridDim.x * blockDim.x) >> 5;
    int per = (N_EDGES + nw - 1) / nw;
    per = (per + 1) & ~1;
    const int e0 = wid * per;
    const int e1 = (e0 + per < N_EDGES) ? (e0 + per) : N_EDGES;
    if (e0 >= e1) return;

    const int* __restrict__ srcp = ei;
    const int* __restrict__ dstp = ei + N_EDGES;
    const float4* __restrict__ eav = reinterpret_cast<const float4*>(ea);
    const float4* __restrict__ x4 = reinterpret_cast<const float4*>(x);

    const int last = e1 - 1;
    int ic = e0 + half;       if (ic > last) ic = last;
    int in_ = e0 + 2 + half;  if (in_ > last) in_ = last;
    int s_nxt = srcp[in_];
    float4 xv_cur = x4[(size_t)srcp[ic] * 16 + sub];

    for (int e = e0; e < e1; e += 2) {
        float4 xv_nxt = x4[(size_t)s_nxt * 16 + sub];
        int i2 = e + 4 + half; if (i2 > last) i2 = last;
        const int s_n2 = srcp[i2];

        const float4 a0 = eav[(size_t)ic * 2];
        const float4 a1 = eav[(size_t)ic * 2 + 1];
        const int d = dstp[ic];

        float ak[8] = {a0.x, a0.y, a0.z, a0.w, a1.x, a1.y, a1.z, a1.w};
        float4 acc = bj;
#pragma unroll
        for (int k = 0; k < 8; k++) {
            acc.x = fmaf(ak[k], w[k].x, acc.x);
            acc.y = fmaf(ak[k], w[k].y, acc.y);
            acc.z = fmaf(ak[k], w[k].z, acc.z);
            acc.w = fmaf(ak[k], w[k].w, acc.w);
        }
        float4 m;
        m.x = fmaxf(xv_cur.x + acc.x, 0.f);
        m.y = fmaxf(xv_cur.y + acc.y, 0.f);
        m.z = fmaxf(xv_cur.z + acc.z, 0.f);
        m.w = fmaxf(xv_cur.w + acc.w, 0.f);
        if (e + half < e1)
            red_add_v4(&agg[(size_t)d * 64 + sub * 4], m);

        xv_cur = xv_nxt;
        ic = in_; in_ = i2; s_nxt = s_n2;
    }
}

// ---------------- edge kernel D=128: one edge per warp, depth-2 gather pipeline ----------------
__global__ __launch_bounds__(256, 4)
void edge_kernel128(const float* __restrict__ x,
                    const int* __restrict__ ei,
                    const float* __restrict__ ea,
                    const float* __restrict__ We,
                    const float* __restrict__ be,
                    float* __restrict__ agg) {
    __shared__ __align__(16) float4 Wes4[8 * 32];
    __shared__ __align__(16) float4 bes4[32];
    for (int i = threadIdx.x; i < 8 * 32; i += blockDim.x)
        Wes4[i] = reinterpret_cast<const float4*>(We)[i];
    if (threadIdx.x < 32) bes4[threadIdx.x] = reinterpret_cast<const float4*>(be)[threadIdx.x];
    __syncthreads();

    const int lane = threadIdx.x & 31;
    float4 w[8];
#pragma unroll
    for (int k = 0; k < 8; k++) w[k] = Wes4[k * 32 + lane];
    const float4 bj = bes4[lane];

    const int wid = (blockIdx.x * blockDim.x + threadIdx.x) >> 5;
    const int nw  = (gridDim.x * blockDim.x) >> 5;
    const int per = (N_EDGES + nw - 1) / nw;
    const int e0  = wid * per;
    const int e1  = (e0 + per < N_EDGES) ? (e0 + per) : N_EDGES;
    if (e0 >= e1) return;

    const int* __restrict__ srcp = ei;
    const int* __restrict__ dstp = ei + N_EDGES;
    const float4* __restrict__ eav = reinterpret_cast<const float4*>(ea);
    const float4* __restrict__ x4 = reinterpret_cast<const float4*>(x);

    const int last = e1 - 1;
    int s_nxt = srcp[(e0 + 1 <= last) ? e0 + 1 : last];
    float4 xv_cur = x4[(size_t)srcp[e0] * 32 + lane];

    for (int e = e0; e < e1; ++e) {
        float4 xv_nxt = x4[(size_t)s_nxt * 32 + lane];
        const int i2 = (e + 2 <= last) ? e + 2 : last;
        const int s_n2 = srcp[i2];

        const float4 a0 = eav[(size_t)e * 2];
        const float4 a1 = eav[(size_t)e * 2 + 1];
        const int d = dstp[e];

        float ak[8] = {a0.x, a0.y, a0.z, a0.w, a1.x, a1.y, a1.z, a1.w};
        float4 acc = bj;
#pragma unroll
        for (int k = 0; k < 8; k++) {
            acc.x = fmaf(ak[k], w[k].x, acc.x);
            acc.y = fmaf(ak[k], w[k].y, acc.y);
            acc.z = fmaf(ak[k], w[k].z, acc.z);
            acc.w = fmaf(ak[k], w[k].w, acc.w);
        }
        float4 m;
        m.x = fmaxf(xv_cur.x + acc.x, 0.f);
        m.y = fmaxf(xv_cur.y + acc.y, 0.f);
        m.z = fmaxf(xv_cur.z + acc.z, 0.f);
        m.w = fmaxf(xv_cur.w + acc.w, 0.f);
        red_add_v4(&agg[(size_t)d * 128 + lane * 4], m);

        xv_cur = xv_nxt;
        s_nxt = s_n2;
    }
}

// ---------------- column-split persistent node kernel ----------------
// Block = 64-node tile x 64 output cols (blockIdx.y = column half).
// smem: W-slice K*64 + inputs 64*K. Lane owns 2 cols (one fma2 accumulator per node).
template <int K, bool POOL>
__global__ void node_kernel(const float* __restrict__ agg,
                            const float* __restrict__ W,
                            const float* __restrict__ b,
                            const int* __restrict__ batch,
                            float* __restrict__ out,
                            float* __restrict__ out2,
                            int ntiles) {
    extern __shared__ __align__(16) float sm[];
    float* Ws  = sm;               // K * 64 (column slice)
    float* ins = sm + K * 64;      // 64 * K
    const int tid = threadIdx.x;
    const int half = blockIdx.y;   // 0 or 1
    constexpr int K4 = K / 4;

    // stage W column-slice: Ws[k][c] = W[k][half*64 + c], c in [0,64)
    const float4* W4 = reinterpret_cast<const float4*>(W);
    float4* Ws4 = reinterpret_cast<float4*>(Ws);
    for (int i = tid; i < K * 16; i += 256) {
        const int k = i >> 4, c4 = i & 15;
        Ws4[i] = W4[k * 32 + half * 16 + c4];
    }

    const int w = tid >> 5, lane = tid & 31;
    const u64 bp = reinterpret_cast<const u64*>(b)[half * 32 + lane];   // (b[2c], b[2c+1])
    const float4* a4 = reinterpret_cast<const float4*>(agg);
    float4* in4 = reinterpret_cast<float4*>(ins);
    const u64* Ws8 = reinterpret_cast<const u64*>(Ws);

    for (int tile = blockIdx.x; tile < ntiles; tile += gridDim.x) {
        const int base = tile * 64;
        __syncthreads();   // W/inputs ready from previous iteration's readers
        for (int i = tid; i < 64 * K4; i += 256) {
            const int r = i / K4, c = i % K4;
            const int n = base + r;
            in4[i] = (n < N_NODES) ? a4[(size_t)n * K4 + c] : make_float4(0.f, 0.f, 0.f, 0.f);
        }
        __syncthreads();

        u64 acc[8];
#pragma unroll
        for (int m = 0; m < 8; m++) acc[m] = bp;

        const float* inrow = ins + (w * 8) * K;
#pragma unroll 1
        for (int k = 0; k < K; k += 4) {
            const u64 w0 = Ws8[(k + 0) * 32 + lane];
            const u64 w1 = Ws8[(k + 1) * 32 + lane];
            const u64 w2 = Ws8[(k + 2) * 32 + lane];
            const u64 w3 = Ws8[(k + 3) * 32 + lane];
#pragma unroll
            for (int m = 0; m < 8; m++) {
                const float4 iv = *reinterpret_cast<const float4*>(inrow + m * K + k);
                acc[m] = fma2(pack2(iv.x, iv.x), w0, acc[m]);
                acc[m] = fma2(pack2(iv.y, iv.y), w1, acc[m]);
                acc[m] = fma2(pack2(iv.z, iv.z), w2, acc[m]);
                acc[m] = fma2(pack2(iv.w, iv.w), w3, acc[m]);
            }
        }

#pragma unroll
        for (int m = 0; m < 8; m++) {
            const int n = base + w * 8 + m;
            if (n < N_NODES) {
                const float2 v = unpack2(acc[m]);
                float2 r;
                r.x = fmaxf(v.x, 0.f);
                r.y = fmaxf(v.y, 0.f);
                if (POOL) {
                    const int g = batch[n];
                    red_add_v2(&g_sums[(size_t)g * HIDDEN + half * 64 + lane * 2], r);
                } else {
                    const size_t o = (size_t)n * 64 + half * 32 + lane;  // float2 index (row=128 floats)
                    reinterpret_cast<float2*>(out)[o]  = r;
                    reinterpret_cast<float2*>(out2)[o] = r;   // agg init for next layer
                }
            }
        }
    }
}

// ---------------- final divide: counts via binary search on sorted batch ----------------
__global__ void div_kernel(const int* __restrict__ batch, float* __restrict__ out) {
    const int g = blockIdx.x;
    const int j = threadIdx.x;
    int lo = 0, hi = N_NODES;
    while (lo < hi) { int mid = (lo + hi) >> 1; if (batch[mid] < g) lo = mid + 1; else hi = mid; }
    const int first = lo;
    lo = first; hi = N_NODES;
    while (lo < hi) { int mid = (lo + hi) >> 1; if (batch[mid] < g + 1) lo = mid + 1; else hi = mid; }
    const float c = fmaxf((float)(lo - first), 1.0f);
    out[g * HIDDEN + j] = g_sums[g * HIDDEN + j] / c;
}

// ---------------- launch ----------------
extern "C" void kernel_launch(void* const* d_in, const int* in_sizes, int n_in,
                              void* d_out, int out_size) {
    const float* x     = (const float*)d_in[0];
    const int*   ei    = (const int*)d_in[1];
    const float* ea    = (const float*)d_in[2];
    const int*   batch = (const int*)d_in[3];
    const float *W1 = (const float*)d_in[4],  *b1 = (const float*)d_in[5];
    const float *We1= (const float*)d_in[6],  *be1= (const float*)d_in[7];
    const float *W2 = (const float*)d_in[8],  *b2 = (const float*)d_in[9];
    const float *We2= (const float*)d_in[10], *be2= (const float*)d_in[11];
    const float *W3 = (const float*)d_in[12], *b3 = (const float*)d_in[13];
    const float *We3= (const float*)d_in[14], *be3= (const float*)d_in[15];
    float* out = (float*)d_out;

    void* p;
    cudaGetSymbolAddress(&p, g_agg1); float* agg1 = (float*)p;
    cudaGetSymbolAddress(&p, g_agg2); float* agg2 = (float*)p;
    cudaGetSymbolAddress(&p, g_agg3); float* agg3 = (float*)p;
    cudaGetSymbolAddress(&p, g_h1);   float* h1   = (float*)p;
    cudaGetSymbolAddress(&p, g_h2);   float* h2   = (float*)p;

    const int smem64  = (64  * 64 + 64 * 64)  * 4;  // 32 KB  -> 7 blocks/SM
    const int smem128 = (128 * 64 + 64 * 128) * 4;  // 64 KB  -> 3 blocks/SM
    cudaFuncSetAttribute(node_kernel<64,  false>, cudaFuncAttributeMaxDynamicSharedMemorySize, smem64);
    cudaFuncSetAttribute(node_kernel<128, false>, cudaFuncAttributeMaxDynamicSharedMemorySize, smem128);
    cudaFuncSetAttribute(node_kernel<128, true >, cudaFuncAttributeMaxDynamicSharedMemorySize, smem128);

    const int EDGE_GRID = 152 * 8;
    const int NTILES    = (N_NODES + 63) / 64;          // 782
    const dim3 NGRID64 (518, 2);                        // 1036 blocks = 7/SM
    const dim3 NGRID128(222, 2);                        // 444 blocks  = 3/SM

    init_agg1_kernel<<<1024, 256>>>(x);                                                    // 1
    edge_kernel64<<<EDGE_GRID, 256>>>(x, ei, ea, We1, be1, agg1);                          // 2
    node_kernel<64, false><<<NGRID64, 256, smem64>>>(agg1, W1, b1, nullptr, h1, agg2, NTILES);   // 3
    edge_kernel128<<<EDGE_GRID, 256>>>(h1, ei, ea, We2, be2, agg2);                        // 4
    node_kernel<128, false><<<NGRID128, 256, smem128>>>(agg2, W2, b2, nullptr, h2, agg3, NTILES); // 5
    edge_kernel128<<<EDGE_GRID, 256>>>(h2, ei, ea, We3, be3, agg3);                        // 6
    zero_pool_kernel<<<32, 256>>>();                                                       // 7
    node_kernel<128, true><<<NGRID128, 256, smem128>>>(agg3, W3, b3, batch, nullptr, nullptr, NTILES); // 8
    div_kernel<<<NUM_GRAPHS, HIDDEN>>>(batch, out);                                        // 9
}